// round 1
// baseline (speedup 1.0000x reference)
#include <cuda_runtime.h>
#include <math.h>

// Problem constants
#define B_  32
#define H_  14
#define W_  14
#define C_  32
#define K_  64
#define KS_ 5
#define OH_ 10
#define OW_ 10
#define P_  100            // OH*OW
#define M_  800            // KS*KS*C
#define N_  196            // H*W

// Scratch (device globals: allocation-guard safe)
__device__ float g_mu_p[B_ * P_ * M_];   // [B,P,M] patches of mu_in
__device__ float g_diag[B_ * P_ * K_];   // diag_vals[b,p,k]

// ---------------------------------------------------------------------------
// Kernel A: one block per (p, b).
//  - gather mu patch + Sigma-diagonal patch into smem
//  - write mu patch row to g_mu_p
//  - mu_out[b,p,k]   = sum_m muP[m] * w[m,k]
//  - v1[b,p,k]       = sum_m dsg[m] * w[m,k]^2
//  - tr[b,p]         = sum_m dsg[m]
//  - g_diag[b,p,k]   = v1 + softplus(w_sigma[k]) * tr
// ---------------------------------------------------------------------------
__global__ void __launch_bounds__(256, 4)
vdp_patch_kernel(const float* __restrict__ mu_in,
                 const float* __restrict__ Sigma_in,
                 const float* __restrict__ w_mu,
                 const float* __restrict__ w_sigma,
                 float* __restrict__ out_mu)
{
    const int p  = blockIdx.x;          // 0..99
    const int b  = blockIdx.y;          // 0..31
    const int oy = p / OW_;
    const int ox = p % OW_;
    const int tid = threadIdx.x;

    __shared__ float sM[M_];
    __shared__ float sD[M_];
    __shared__ float redMu[256];
    __shared__ float redV[256];
    __shared__ float redT[256];

    float* mup = g_mu_p + (size_t)(b * P_ + p) * M_;

    float trp = 0.0f;
    for (int m = tid; m < M_; m += 256) {
        const int i = m / (KS_ * C_);          // kernel row
        const int j = (m / C_) % KS_;          // kernel col
        const int c = m & (C_ - 1);
        const int h = oy + i;
        const int w = ox + j;

        const float mu = mu_in[((b * H_ + h) * W_ + w) * C_ + c];
        sM[m]  = mu;
        mup[m] = mu;

        const int n = h * W_ + w;
        const float ds = Sigma_in[(((size_t)b * N_ + n) * N_ + n) * C_ + c];
        sD[m] = ds;
        trp  += ds;
    }
    redT[tid] = trp;
    __syncthreads();

    // block-reduce tr
    for (int s = 128; s > 0; s >>= 1) {
        if (tid < s) redT[tid] += redT[tid + s];
        __syncthreads();
    }
    const float tr = redT[0];

    // 256 threads = 64 k-values x 4 M-quarters
    const int k       = tid & 63;
    const int quarter = tid >> 6;
    const int m0      = quarter * (M_ / 4);

    float aMu = 0.0f, aV = 0.0f;
    #pragma unroll 4
    for (int m = m0; m < m0 + (M_ / 4); ++m) {
        const float wv = w_mu[m * K_ + k];     // coalesced across k
        aMu = fmaf(sM[m], wv, aMu);
        aV  = fmaf(sD[m], wv * wv, aV);
    }
    redMu[tid] = aMu;
    redV[tid]  = aV;
    __syncthreads();

    if (tid < K_) {
        const float mo = redMu[tid] + redMu[tid + 64] + redMu[tid + 128] + redMu[tid + 192];
        const float v1 = redV[tid]  + redV[tid + 64]  + redV[tid + 128]  + redV[tid + 192];
        const float sp = log1pf(expf(w_sigma[tid]));       // softplus
        const size_t base = (size_t)(b * P_ + p) * K_;
        out_mu[base + tid] = mo;
        g_diag[base + tid] = v1 + sp * tr;
    }
}

// ---------------------------------------------------------------------------
// Kernel B: Gram matrix G[b,p,q] = <mu_p[b,p,:], mu_p[b,q,:]> and the full
// Sigma_out write.  One block per (b, 25x25 (p,q) tile). 640 threads; threads
// 0..624 each own one (p,q).
// Sigma_out[b,p,q,k] = sp[k]*G + (p==q ? diag_vals[b,p,k] : 0)
//   -> finite cleanup -> abs where k==q (<64)     [reference order preserved]
// ---------------------------------------------------------------------------
#define TP 25
#define MCHUNK 160
#define LDT (MCHUNK + 1)   // 161: 161 % 32 == 1 -> conflict-free q-strides

__global__ void __launch_bounds__(640, 2)
vdp_gram_kernel(const float* __restrict__ w_sigma,
                float* __restrict__ out_sig)
{
    const int b  = blockIdx.y;
    const int pt = blockIdx.x >> 2;     // 0..3
    const int qt = blockIdx.x & 3;      // 0..3
    const int tid = threadIdx.x;

    __shared__ float aS[TP * LDT];
    __shared__ float bS[TP * LDT];
    __shared__ float spS[K_];

    if (tid < K_) spS[tid] = log1pf(expf(w_sigma[tid]));

    const float* aG = g_mu_p + (size_t)(b * P_ + pt * TP) * M_;
    const float* bG = g_mu_p + (size_t)(b * P_ + qt * TP) * M_;

    const int p = tid / TP;   // valid when tid < 625
    const int q = tid % TP;

    float g = 0.0f;

    for (int mc = 0; mc < M_; mc += MCHUNK) {
        __syncthreads();   // protect prior-iteration smem reads (and spS on iter 0)
        for (int idx = tid; idx < TP * MCHUNK; idx += 640) {
            const int r  = idx / MCHUNK;
            const int mm = idx - r * MCHUNK;
            aS[r * LDT + mm] = aG[(size_t)r * M_ + mc + mm];
            bS[r * LDT + mm] = bG[(size_t)r * M_ + mc + mm];
        }
        __syncthreads();

        if (tid < TP * TP) {
            const float* ap = aS + p * LDT;
            const float* bp = bS + q * LDT;
            #pragma unroll 8
            for (int m = 0; m < MCHUNK; ++m)
                g = fmaf(ap[m], bp[m], g);
        }
    }

    if (tid < TP * TP) {
        const int pg = pt * TP + p;
        const int qg = qt * TP + q;
        const bool dgn = (pg == qg);
        const float* dv = g_diag + (size_t)(b * P_ + pg) * K_;

        float4* outp = (float4*)(out_sig + (((size_t)(b * P_) + pg) * P_ + qg) * K_);

        #pragma unroll
        for (int k4 = 0; k4 < K_ / 4; ++k4) {
            float4 v;
            float* vv = (float*)&v;
            #pragma unroll
            for (int l = 0; l < 4; ++l) {
                const int k = k4 * 4 + l;
                float val = spS[k] * g;
                if (dgn) val += dv[k];
                if (!isfinite(val)) val = 0.0f;
                if (k == qg) val = fabsf(val);   // set_diag(abs) on inner [P,K]
                vv[l] = val;
            }
            outp[k4] = v;
        }
    }
}

// ---------------------------------------------------------------------------
extern "C" void kernel_launch(void* const* d_in, const int* in_sizes, int n_in,
                              void* d_out, int out_size)
{
    // Dispatch inputs by element count (all four sizes are distinct).
    const float* mu_in    = nullptr;   // 32*14*14*32    = 200704
    const float* Sigma_in = nullptr;   // 32*196*196*32  = 39337984
    const float* w_mu     = nullptr;   // 5*5*32*64      = 51200
    const float* w_sigma  = nullptr;   // 64
    for (int i = 0; i < n_in; ++i) {
        switch (in_sizes[i]) {
            case 200704:   mu_in    = (const float*)d_in[i]; break;
            case 39337984: Sigma_in = (const float*)d_in[i]; break;
            case 51200:    w_mu     = (const float*)d_in[i]; break;
            case 64:       w_sigma  = (const float*)d_in[i]; break;
        }
    }

    float* out     = (float*)d_out;
    float* out_mu  = out;                       // [B,10,10,64]  = 204800
    float* out_sig = out + (size_t)B_ * P_ * K_; // [B,100,100,64] = 20480000

    vdp_patch_kernel<<<dim3(P_, B_), 256>>>(mu_in, Sigma_in, w_mu, w_sigma, out_mu);
    vdp_gram_kernel<<<dim3(16, B_), 640>>>(w_sigma, out_sig);
}

// round 2
// speedup vs baseline: 1.1811x; 1.1811x over previous
#include <cuda_runtime.h>
#include <math.h>

#define B_  32
#define H_  14
#define W_  14
#define C_  32
#define K_  64
#define KS_ 5
#define P_  100
#define M_  800
#define N_  196
#define NROWS (B_ * P_)        // 3200

// Scratch (device globals: allocation-guard safe)
__device__ float g_mu_p[NROWS * M_];   // [row, M] mu patches
__device__ float g_dsg [NROWS * M_];   // [row, M] Sigma-diag patches
__device__ float g_tr  [NROWS];        // trace per row
__device__ float g_diag[NROWS * K_];   // diag_vals

// ---------------------------------------------------------------------------
// Kernel 1: gather patches (mu + Sigma-diagonal) + per-row trace.
// grid (P, B), 128 threads. All loads/stores are float4 over the contiguous
// channel dim.
// ---------------------------------------------------------------------------
__global__ void __launch_bounds__(128)
k_gather(const float* __restrict__ mu_in, const float* __restrict__ Sigma_in)
{
    const int p = blockIdx.x, b = blockIdx.y;
    const int oy = p / 10, ox = p % 10;
    const int row = b * P_ + p;
    __shared__ float red[128];

    float4* mup = (float4*)(g_mu_p + (size_t)row * M_);
    float4* dsp = (float4*)(g_dsg + (size_t)row * M_);

    float tr = 0.0f;
    for (int m4 = threadIdx.x; m4 < 200; m4 += 128) {     // m = 4*m4, (i,j,c) order
        const int c4 = m4 & 7;
        const int ij = m4 >> 3;
        const int j = ij % 5, i = ij / 5;
        const int h = oy + i, w = ox + j;

        const float4 mu = *(const float4*)(mu_in + (((b * H_ + h) * W_ + w) * C_) + c4 * 4);
        const int n = h * W_ + w;
        const float4 ds = *(const float4*)(Sigma_in + (((size_t)(b * N_ + n)) * N_ + n) * C_ + c4 * 4);

        mup[m4] = mu;
        dsp[m4] = ds;
        tr += ds.x + ds.y + ds.z + ds.w;
    }
    red[threadIdx.x] = tr;
    __syncthreads();
    for (int s = 64; s > 0; s >>= 1) {
        if (threadIdx.x < s) red[threadIdx.x] += red[threadIdx.x + s];
        __syncthreads();
    }
    if (threadIdx.x == 0) g_tr[row] = red[0];
}

// ---------------------------------------------------------------------------
// Kernel 2: dual GEMM.
//   mu_out[row,k]  = sum_m A[row,m] * W[m,k]
//   diag [row,k]   = sum_m D[row,m] * W[m,k]^2  +  softplus(w_sigma[k]) * tr[row]
// Block: 16 rows x 32 k (k-half selected by blockIdx), 64 threads,
// micro-tile 2 rows x 4 k. W chunk staged in smem (reused by all 16 rows).
// 400 blocks total for wave balance.
// ---------------------------------------------------------------------------
#define A2_MC 100

__global__ void __launch_bounds__(64)
k_dualgemm(const float* __restrict__ w_mu, const float* __restrict__ w_sigma,
           float* __restrict__ out_mu)
{
    const int rt  = blockIdx.x >> 1;        // 0..199
    const int kh  = blockIdx.x & 1;         // k half
    const int row0 = rt * 16;
    const int tid = threadIdx.x;
    const int kq = tid & 7;                  // k quad (4 k each)
    const int rp = tid >> 3;                 // row pair (2 rows each)

    __shared__ float sA[16 * A2_MC];
    __shared__ float sD[16 * A2_MC];
    __shared__ float sW[A2_MC * 32];

    float accm[2][4] = {{0}};
    float accv[2][4] = {{0}};

    for (int mc = 0; mc < M_; mc += A2_MC) {
        __syncthreads();
        for (int idx = tid; idx < 400; idx += 64) {          // 16x100 floats as float4
            const int r = idx / 25, c4 = idx % 25;
            ((float4*)sA)[r * 25 + c4] = *(const float4*)(g_mu_p + (size_t)(row0 + r) * M_ + mc + c4 * 4);
            ((float4*)sD)[r * 25 + c4] = *(const float4*)(g_dsg + (size_t)(row0 + r) * M_ + mc + c4 * 4);
        }
        for (int idx = tid; idx < 800; idx += 64) {          // 100x32 floats as float4
            const int m = idx >> 3, c4 = idx & 7;
            ((float4*)sW)[m * 8 + c4] = *(const float4*)(w_mu + (size_t)(mc + m) * K_ + kh * 32 + c4 * 4);
        }
        __syncthreads();

        #pragma unroll 4
        for (int m = 0; m < A2_MC; ++m) {
            const float4 w = *(float4*)&sW[m * 32 + kq * 4];
            float4 w2;
            w2.x = w.x * w.x; w2.y = w.y * w.y; w2.z = w.z * w.z; w2.w = w.w * w.w;
            #pragma unroll
            for (int i = 0; i < 2; ++i) {
                const float a = sA[(rp * 2 + i) * A2_MC + m];
                const float d = sD[(rp * 2 + i) * A2_MC + m];
                accm[i][0] = fmaf(a, w.x, accm[i][0]);
                accm[i][1] = fmaf(a, w.y, accm[i][1]);
                accm[i][2] = fmaf(a, w.z, accm[i][2]);
                accm[i][3] = fmaf(a, w.w, accm[i][3]);
                accv[i][0] = fmaf(d, w2.x, accv[i][0]);
                accv[i][1] = fmaf(d, w2.y, accv[i][1]);
                accv[i][2] = fmaf(d, w2.z, accv[i][2]);
                accv[i][3] = fmaf(d, w2.w, accv[i][3]);
            }
        }
    }

    // epilogue
    const int k0 = kh * 32 + kq * 4;
    float sp0 = log1pf(expf(w_sigma[k0 + 0]));
    float sp1 = log1pf(expf(w_sigma[k0 + 1]));
    float sp2 = log1pf(expf(w_sigma[k0 + 2]));
    float sp3 = log1pf(expf(w_sigma[k0 + 3]));
    #pragma unroll
    for (int i = 0; i < 2; ++i) {
        const int row = row0 + rp * 2 + i;
        const float trv = g_tr[row];
        float4 mo = make_float4(accm[i][0], accm[i][1], accm[i][2], accm[i][3]);
        *(float4*)(out_mu + (size_t)row * K_ + k0) = mo;
        float4 dg = make_float4(fmaf(sp0, trv, accv[i][0]),
                                fmaf(sp1, trv, accv[i][1]),
                                fmaf(sp2, trv, accv[i][2]),
                                fmaf(sp3, trv, accv[i][3]));
        *(float4*)(g_diag + (size_t)row * K_ + k0) = dg;
    }
}

// ---------------------------------------------------------------------------
// Kernel 3: Gram + Sigma_out write.
// G[b,p,q] = <mu_p[b,p,:], mu_p[b,q,:]>
// Sigma_out[b,p,q,k] = sp[k]*G (+ diag_vals if p==q) -> finite cleanup ->
//                       abs where k==q (<64).
// Tile: 52x52 (2x2 tiles cover P=100, masked), 192 threads, 169 active in
// compute with 4x4 micro-tiles (rows strided by 13 for conflict-free LDS).
// ---------------------------------------------------------------------------
#define GT   52
#define GMC  100
#define GLDT 102     // floats; 102 mod 32 = 6, distinct banks for 13 lanes

__global__ void __launch_bounds__(192)
k_gram(const float* __restrict__ w_sigma, float* __restrict__ out_sig)
{
    const int b  = blockIdx.y;
    const int pt = blockIdx.x >> 1;
    const int qt = blockIdx.x & 1;
    const int tid = threadIdx.x;

    __shared__ float aS[GT * GLDT];
    __shared__ float bS[GT * GLDT];
    __shared__ float spS[K_];

    if (tid < K_) spS[tid] = log1pf(expf(w_sigma[tid]));

    const int tx = tid % 13;
    const int ty = tid / 13;

    float acc[4][4] = {{0}};

    for (int mc = 0; mc < M_; mc += GMC) {
        __syncthreads();
        for (int idx = tid; idx < GT * GMC / 2; idx += 192) {   // 2600 float2
            const int r = idx / 50, c2 = idx % 50;
            const int pr = pt * GT + r;
            const int qr = qt * GT + r;
            float2 va = (pr < P_)
                ? *(const float2*)(g_mu_p + (size_t)(b * P_ + pr) * M_ + mc + c2 * 2)
                : make_float2(0.f, 0.f);
            float2 vb = (qr < P_)
                ? *(const float2*)(g_mu_p + (size_t)(b * P_ + qr) * M_ + mc + c2 * 2)
                : make_float2(0.f, 0.f);
            *(float2*)(aS + r * GLDT + c2 * 2) = va;
            *(float2*)(bS + r * GLDT + c2 * 2) = vb;
        }
        __syncthreads();

        if (tid < 169) {
            #pragma unroll 2
            for (int m2 = 0; m2 < GMC / 2; ++m2) {
                float2 av[4], bv[4];
                #pragma unroll
                for (int u = 0; u < 4; ++u)
                    av[u] = *(float2*)(aS + (tx + 13 * u) * GLDT + m2 * 2);
                #pragma unroll
                for (int v = 0; v < 4; ++v)
                    bv[v] = *(float2*)(bS + (ty + 13 * v) * GLDT + m2 * 2);
                #pragma unroll
                for (int u = 0; u < 4; ++u)
                    #pragma unroll
                    for (int v = 0; v < 4; ++v) {
                        acc[u][v] = fmaf(av[u].x, bv[v].x, acc[u][v]);
                        acc[u][v] = fmaf(av[u].y, bv[v].y, acc[u][v]);
                    }
            }
        }
    }

    if (tid < 169) {
        #pragma unroll
        for (int u = 0; u < 4; ++u) {
            const int pg = pt * GT + tx + 13 * u;
            if (pg >= P_) continue;
            const float* dv = g_diag + (size_t)(b * P_ + pg) * K_;
            #pragma unroll
            for (int v = 0; v < 4; ++v) {
                const int qg = qt * GT + ty + 13 * v;
                if (qg >= P_) continue;
                const float g = acc[u][v];
                const bool dgn = (pg == qg);
                float4* outp = (float4*)(out_sig + (((size_t)(b * P_) + pg) * P_ + qg) * K_);
                #pragma unroll
                for (int k4 = 0; k4 < K_ / 4; ++k4) {
                    float4 o;
                    float* ov = (float*)&o;
                    #pragma unroll
                    for (int l = 0; l < 4; ++l) {
                        const int k = k4 * 4 + l;
                        float val = spS[k] * g;
                        if (dgn) val += dv[k];
                        if (!isfinite(val)) val = 0.0f;
                        if (k == qg) val = fabsf(val);
                        ov[l] = val;
                    }
                    outp[k4] = o;
                }
            }
        }
    }
}

// ---------------------------------------------------------------------------
extern "C" void kernel_launch(void* const* d_in, const int* in_sizes, int n_in,
                              void* d_out, int out_size)
{
    const float* mu_in    = nullptr;   // 200704
    const float* Sigma_in = nullptr;   // 39337984
    const float* w_mu     = nullptr;   // 51200
    const float* w_sigma  = nullptr;   // 64
    for (int i = 0; i < n_in; ++i) {
        switch (in_sizes[i]) {
            case 200704:   mu_in    = (const float*)d_in[i]; break;
            case 39337984: Sigma_in = (const float*)d_in[i]; break;
            case 51200:    w_mu     = (const float*)d_in[i]; break;
            case 64:       w_sigma  = (const float*)d_in[i]; break;
        }
    }

    float* out     = (float*)d_out;
    float* out_mu  = out;                         // [32,10,10,64]
    float* out_sig = out + (size_t)B_ * P_ * K_;  // [32,100,100,64]

    k_gather  <<<dim3(P_, B_), 128>>>(mu_in, Sigma_in);
    k_dualgemm<<<400, 64>>>(w_mu, w_sigma, out_mu);
    k_gram    <<<dim3(4, B_), 192>>>(w_sigma, out_sig);
}

// round 4
// speedup vs baseline: 2.1820x; 1.8475x over previous
#include <cuda_runtime.h>
#include <math.h>
#include <stdint.h>

#define B_  32
#define H_  14
#define W_  14
#define C_  32
#define K_  64
#define P_  100
#define M_  800
#define N_  196
#define NROWS (B_ * P_)      // 3200
#define GSPLIT 4             // Gram M-splits of 200
#define VSPLIT 2             // mu/v M-splits of 400

// ---------------- scratch (device globals; allocation-guard safe) ----------
__device__ float g_mu_p[NROWS * M_];               // mu patches  [row, M]
__device__ float g_dsg [NROWS * M_];               // Sigma-diag patches
__device__ float g_tr  [NROWS];                    // trace per row
__device__ float g_G   [GSPLIT * B_ * P_ * 128];   // partial Gram (128-col stride)
__device__ float g_pmu [VSPLIT * NROWS * K_];      // partial mu
__device__ float g_pv  [VSPLIT * NROWS * K_];      // partial v1

// ---------------- helpers ---------------------------------------------------
__device__ __forceinline__ uint32_t f2tf(float f) {
    uint32_t u; asm("cvt.rna.tf32.f32 %0, %1;" : "=r"(u) : "f"(f)); return u;
}
__device__ __forceinline__ void mma16n8k8(float* d, const uint32_t* a, const uint32_t* b) {
    asm volatile("mma.sync.aligned.m16n8k8.row.col.f32.tf32.tf32.f32 "
                 "{%0,%1,%2,%3}, {%4,%5,%6,%7}, {%8,%9}, {%0,%1,%2,%3};"
                 : "+f"(d[0]), "+f"(d[1]), "+f"(d[2]), "+f"(d[3])
                 : "r"(a[0]), "r"(a[1]), "r"(a[2]), "r"(a[3]), "r"(b[0]), "r"(b[1]));
}

// ---------------------------------------------------------------------------
// Kernel 1: gather patches (mu + Sigma-diagonal) + per-row trace.
// ---------------------------------------------------------------------------
__global__ void __launch_bounds__(128)
k_gather(const float* __restrict__ mu_in, const float* __restrict__ Sigma_in)
{
    const int p = blockIdx.x, b = blockIdx.y;
    const int oy = p / 10, ox = p % 10;
    const int row = b * P_ + p;
    __shared__ float red[128];

    float4* mup = (float4*)(g_mu_p + (size_t)row * M_);
    float4* dsp = (float4*)(g_dsg + (size_t)row * M_);

    float tr = 0.0f;
    for (int m4 = threadIdx.x; m4 < 200; m4 += 128) {
        const int c4 = m4 & 7;
        const int ij = m4 >> 3;
        const int j = ij % 5, i = ij / 5;
        const int h = oy + i, w = ox + j;
        const float4 mu = *(const float4*)(mu_in + (((b * H_ + h) * W_ + w) * C_) + c4 * 4);
        const int n = h * W_ + w;
        const float4 ds = *(const float4*)(Sigma_in + (((size_t)(b * N_ + n)) * N_ + n) * C_ + c4 * 4);
        mup[m4] = mu;
        dsp[m4] = ds;
        tr += ds.x + ds.y + ds.z + ds.w;
    }
    red[threadIdx.x] = tr;
    __syncthreads();
    for (int s = 64; s > 0; s >>= 1) {
        if (threadIdx.x < s) red[threadIdx.x] += red[threadIdx.x + s];
        __syncthreads();
    }
    if (threadIdx.x == 0) g_tr[row] = red[0];
}

// ---------------------------------------------------------------------------
// Kernel 2: Gram via mma.sync tf32, 3xTF32 hi/lo.
// Grid: 32 batches x 4 M-splits. Block 256 thr = 8 warps (2 m-groups x 4 n).
// Each warp: 4x4 tiles of m16n8. A staged (128 rows x 40, stride 44).
// ---------------------------------------------------------------------------
#define GMC   40
#define GSTR  44

__device__ __forceinline__ void gram_pass(const uint32_t* Aarr, const uint32_t* Barr,
                                          float (&acc)[4][4][4],
                                          int wm, int wn, int g, int tig, int col)
{
    uint32_t af[4][4], bf[4][2];
    #pragma unroll
    for (int i = 0; i < 4; ++i) {
        const int rm = 16 * (wm + 2 * i);
        af[i][0] = Aarr[(rm + g) * GSTR + col + tig];
        af[i][1] = Aarr[(rm + g + 8) * GSTR + col + tig];
        af[i][2] = Aarr[(rm + g) * GSTR + col + tig + 4];
        af[i][3] = Aarr[(rm + g + 8) * GSTR + col + tig + 4];
    }
    #pragma unroll
    for (int j = 0; j < 4; ++j) {
        const int nb = 8 * (wn + 4 * j);
        bf[j][0] = Barr[(nb + g) * GSTR + col + tig];
        bf[j][1] = Barr[(nb + g) * GSTR + col + tig + 4];
    }
    #pragma unroll
    for (int i = 0; i < 4; ++i)
        #pragma unroll
        for (int j = 0; j < 4; ++j)
            mma16n8k8(acc[i][j], af[i], bf[j]);
}

__global__ void __launch_bounds__(256)
k_gram_mma()
{
    __shared__ uint32_t Ahi[128 * GSTR];
    __shared__ uint32_t Alo[128 * GSTR];

    const int b = blockIdx.x >> 2;
    const int s = blockIdx.x & 3;
    const int m0base = s * 200;
    const int tid = threadIdx.x;
    const int lane = tid & 31, warp = tid >> 5;
    const int g = lane >> 2, tig = lane & 3;
    const int wm = warp & 1, wn = warp >> 1;

    float acc[4][4][4] = {{{0}}};

    for (int c = 0; c < 5; ++c) {
        const int m0 = m0base + c * GMC;
        __syncthreads();
        // stage 128 rows x 40 floats (rows >= 100 zero), hi/lo tf32
        #pragma unroll
        for (int it = 0; it < 5; ++it) {
            const int idx = it * 256 + tid;          // 1280 float4 slots
            const int r = idx / 10, c4 = idx % 10;
            float4 v = make_float4(0.f, 0.f, 0.f, 0.f);
            if (r < P_)
                v = *(const float4*)(g_mu_p + (size_t)(b * P_ + r) * M_ + m0 + c4 * 4);
            uint4 hi, lo;
            hi.x = f2tf(v.x); hi.y = f2tf(v.y); hi.z = f2tf(v.z); hi.w = f2tf(v.w);
            lo.x = f2tf(v.x - __uint_as_float(hi.x));
            lo.y = f2tf(v.y - __uint_as_float(hi.y));
            lo.z = f2tf(v.z - __uint_as_float(hi.z));
            lo.w = f2tf(v.w - __uint_as_float(hi.w));
            *(uint4*)(Ahi + r * GSTR + c4 * 4) = hi;
            *(uint4*)(Alo + r * GSTR + c4 * 4) = lo;
        }
        __syncthreads();

        #pragma unroll
        for (int ks = 0; ks < 5; ++ks) {
            const int col = ks * 8;
            gram_pass(Ahi, Ahi, acc, wm, wn, g, tig, col);   // hh
            gram_pass(Ahi, Alo, acc, wm, wn, g, tig, col);   // hl
            gram_pass(Alo, Ahi, acc, wm, wn, g, tig, col);   // lh
        }
    }

    float* Gb = g_G + (size_t)(s * B_ + b) * P_ * 128;
    #pragma unroll
    for (int i = 0; i < 4; ++i) {
        const int pr = 16 * (wm + 2 * i) + g;
        #pragma unroll
        for (int j = 0; j < 4; ++j) {
            const int qc = 8 * (wn + 4 * j) + 2 * tig;
            if (pr < P_ && qc < P_)     Gb[(size_t)pr * 128 + qc]           = acc[i][j][0];
            if (pr < P_ && qc + 1 < P_) Gb[(size_t)pr * 128 + qc + 1]       = acc[i][j][1];
            if (pr + 8 < P_ && qc < P_)     Gb[(size_t)(pr + 8) * 128 + qc]     = acc[i][j][2];
            if (pr + 8 < P_ && qc + 1 < P_) Gb[(size_t)(pr + 8) * 128 + qc + 1] = acc[i][j][3];
        }
    }
}

// ---------------------------------------------------------------------------
// Kernel 3: mu (3xTF32) + v1 (1xTF32) dual GEMM via mma.sync.
// Grid: 50 row-blocks (64 rows) x 2 M-splits. 128 thr = 4 warps (one m-tile
// pair each: warp = m-tile). Wt chunk staged [64 k][40 m].
// ---------------------------------------------------------------------------
#define VMC 40
// dynamic smem layout (uint32 units), each array 64*44 = 2816
#define O_AHI 0
#define O_ALO 2816
#define O_DD  5632
#define O_WH  8448
#define O_WL  11264
#define O_W2  14080
#define VSMEM_BYTES (16896 * 4)

__global__ void __launch_bounds__(128)
k_muv_mma(const float* __restrict__ w_mu)
{
    extern __shared__ uint32_t vs[];
    const int rb = blockIdx.x >> 1;
    const int s2 = blockIdx.x & 1;
    const int row0 = rb * 64;
    const int m0base = s2 * 400;
    const int tid = threadIdx.x;
    const int lane = tid & 31, warp = tid >> 5;
    const int g = lane >> 2, tig = lane & 3;

    float accm[8][4] = {{0}};
    float accv[8][4] = {{0}};

    for (int c = 0; c < 10; ++c) {
        const int m0 = m0base + c * VMC;
        __syncthreads();
        // stage A/D rows 64 x 40 (640 float4 slots)
        #pragma unroll
        for (int it = 0; it < 5; ++it) {
            const int idx = it * 128 + tid;
            const int r = idx / 10, c4 = idx % 10;
            const size_t off = (size_t)(row0 + r) * M_ + m0 + c4 * 4;
            const float4 va = *(const float4*)(g_mu_p + off);
            const float4 vd = *(const float4*)(g_dsg + off);
            uint4 hi, lo, dd;
            hi.x = f2tf(va.x); hi.y = f2tf(va.y); hi.z = f2tf(va.z); hi.w = f2tf(va.w);
            lo.x = f2tf(va.x - __uint_as_float(hi.x));
            lo.y = f2tf(va.y - __uint_as_float(hi.y));
            lo.z = f2tf(va.z - __uint_as_float(hi.z));
            lo.w = f2tf(va.w - __uint_as_float(hi.w));
            dd.x = f2tf(vd.x); dd.y = f2tf(vd.y); dd.z = f2tf(vd.z); dd.w = f2tf(vd.w);
            *(uint4*)(vs + O_AHI + r * GSTR + c4 * 4) = hi;
            *(uint4*)(vs + O_ALO + r * GSTR + c4 * 4) = lo;
            *(uint4*)(vs + O_DD  + r * GSTR + c4 * 4) = dd;
        }
        // stage Wt [64 k][40 m] hi/lo/sq; gmem coalesced over k
        #pragma unroll
        for (int it = 0; it < 20; ++it) {
            const int idx = it * 128 + tid;          // 2560 scalars
            const int mm = idx >> 6, k = idx & 63;
            const float w = w_mu[(size_t)(m0 + mm) * K_ + k];
            const uint32_t wh = f2tf(w);
            vs[O_WH + k * GSTR + mm] = wh;
            vs[O_WL + k * GSTR + mm] = f2tf(w - __uint_as_float(wh));
            vs[O_W2 + k * GSTR + mm] = f2tf(w * w);
        }
        __syncthreads();

        #pragma unroll
        for (int ks = 0; ks < 5; ++ks) {
            const int col = ks * 8;
            const int rm = 16 * warp;
            uint32_t ah[4], al[4], dd[4];
            ah[0] = vs[O_AHI + (rm + g) * GSTR + col + tig];
            ah[1] = vs[O_AHI + (rm + g + 8) * GSTR + col + tig];
            ah[2] = vs[O_AHI + (rm + g) * GSTR + col + tig + 4];
            ah[3] = vs[O_AHI + (rm + g + 8) * GSTR + col + tig + 4];
            al[0] = vs[O_ALO + (rm + g) * GSTR + col + tig];
            al[1] = vs[O_ALO + (rm + g + 8) * GSTR + col + tig];
            al[2] = vs[O_ALO + (rm + g) * GSTR + col + tig + 4];
            al[3] = vs[O_ALO + (rm + g + 8) * GSTR + col + tig + 4];
            dd[0] = vs[O_DD + (rm + g) * GSTR + col + tig];
            dd[1] = vs[O_DD + (rm + g + 8) * GSTR + col + tig];
            dd[2] = vs[O_DD + (rm + g) * GSTR + col + tig + 4];
            dd[3] = vs[O_DD + (rm + g + 8) * GSTR + col + tig + 4];
            #pragma unroll
            for (int nt = 0; nt < 8; ++nt) {
                const int nb = 8 * nt;
                uint32_t bh[2], bl[2], b2[2];
                bh[0] = vs[O_WH + (nb + g) * GSTR + col + tig];
                bh[1] = vs[O_WH + (nb + g) * GSTR + col + tig + 4];
                bl[0] = vs[O_WL + (nb + g) * GSTR + col + tig];
                bl[1] = vs[O_WL + (nb + g) * GSTR + col + tig + 4];
                b2[0] = vs[O_W2 + (nb + g) * GSTR + col + tig];
                b2[1] = vs[O_W2 + (nb + g) * GSTR + col + tig + 4];
                mma16n8k8(accm[nt], ah, bh);
                mma16n8k8(accm[nt], ah, bl);
                mma16n8k8(accm[nt], al, bh);
                mma16n8k8(accv[nt], dd, b2);
            }
        }
    }

    // store partials
    const int r0 = row0 + 16 * warp + g;
    #pragma unroll
    for (int nt = 0; nt < 8; ++nt) {
        const int k0 = 8 * nt + 2 * tig;
        float* pm0 = g_pmu + (size_t)(s2 * NROWS + r0) * K_ + k0;
        float* pv0 = g_pv  + (size_t)(s2 * NROWS + r0) * K_ + k0;
        pm0[0] = accm[nt][0]; pm0[1] = accm[nt][1];
        pm0[8 * K_ + 0] = accm[nt][2]; pm0[8 * K_ + 1] = accm[nt][3];
        pv0[0] = accv[nt][0]; pv0[1] = accv[nt][1];
        pv0[8 * K_ + 0] = accv[nt][2]; pv0[8 * K_ + 1] = accv[nt][3];
    }
}

// ---------------------------------------------------------------------------
// Kernel 4: epilogue. One block per (p, b). Sums partials, computes mu_out,
// diag, then streams Sigma_out row with exact reference semantics.
// ---------------------------------------------------------------------------
__global__ void __launch_bounds__(256)
k_epi(const float* __restrict__ w_sigma,
      float* __restrict__ out_mu, float* __restrict__ out_sig)
{
    const int p = blockIdx.x, b = blockIdx.y;
    const int tid = threadIdx.x;
    const int row = b * P_ + p;

    __shared__ float sG[P_];
    __shared__ float sSp[K_];
    __shared__ float sDiag[K_];

    if (tid < K_) {
        float pm = 0.f, pv = 0.f;
        #pragma unroll
        for (int s = 0; s < VSPLIT; ++s) {
            const size_t o = (size_t)(s * NROWS + row) * K_ + tid;
            pm += g_pmu[o];
            pv += g_pv[o];
        }
        const float sp = log1pf(expf(w_sigma[tid]));
        out_mu[(size_t)row * K_ + tid] = pm;
        sSp[tid] = sp;
        sDiag[tid] = pv + sp * g_tr[row];
    }
    if (tid < P_) {
        float gq = 0.f;
        #pragma unroll
        for (int s = 0; s < GSPLIT; ++s)
            gq += g_G[((size_t)(s * B_ + b) * P_ + p) * 128 + tid];
        sG[tid] = gq;
    }
    __syncthreads();

    float* outr = out_sig + ((size_t)row * P_) * K_;
    #pragma unroll 7
    for (int j = 0; j < 7; ++j) {
        const int idx = j * 256 + tid;      // 100*16 float4 slots
        if (idx >= P_ * 16) break;
        const int q = idx >> 4;
        const int k0 = (idx & 15) * 4;
        const float gq = sG[q];
        const bool dgn = (q == p);
        float4 o;
        float* ov = (float*)&o;
        #pragma unroll
        for (int l = 0; l < 4; ++l) {
            const int k = k0 + l;
            float v = sSp[k] * gq;
            if (dgn) v += sDiag[k];
            if (!isfinite(v)) v = 0.0f;
            if (k == q) v = fabsf(v);
            ov[l] = v;
        }
        *(float4*)(outr + (size_t)q * K_ + k0) = o;
    }
}

// ---------------------------------------------------------------------------
extern "C" void kernel_launch(void* const* d_in, const int* in_sizes, int n_in,
                              void* d_out, int out_size)
{
    const float* mu_in    = nullptr;   // 200704
    const float* Sigma_in = nullptr;   // 39337984
    const float* w_mu     = nullptr;   // 51200
    const float* w_sigma  = nullptr;   // 64
    for (int i = 0; i < n_in; ++i) {
        switch (in_sizes[i]) {
            case 200704:   mu_in    = (const float*)d_in[i]; break;
            case 39337984: Sigma_in = (const float*)d_in[i]; break;
            case 51200:    w_mu     = (const float*)d_in[i]; break;
            case 64:       w_sigma  = (const float*)d_in[i]; break;
        }
    }

    float* out     = (float*)d_out;
    float* out_mu  = out;                         // [32,10,10,64]
    float* out_sig = out + (size_t)B_ * P_ * K_;  // [32,100,100,64]

    static bool attr_done = false;
    if (!attr_done) {
        cudaFuncSetAttribute(k_muv_mma, cudaFuncAttributeMaxDynamicSharedMemorySize, VSMEM_BYTES);
        attr_done = true;
    }

    k_gather  <<<dim3(P_, B_), 128>>>(mu_in, Sigma_in);
    k_gram_mma<<<B_ * GSPLIT, 256>>>();
    k_muv_mma <<<P_, 128, VSMEM_BYTES>>>(w_mu);
    k_epi     <<<dim3(P_, B_), 256>>>(w_sigma, out_mu, out_sig);
}